// round 14
// baseline (speedup 1.0000x reference)
#include <cuda_runtime.h>
#include <cstdint>

// Problem constants
#define BSZ    4096
#define DD     256
#define MARGIN 0.5f

// GEMM tiling
#define BM 128
#define BN 128
#define BK 16
#define NT (DD / BK)        // 16 k-tiles
#define NTILES (BSZ / BM)   // 32 tile-blocks per dim
#define NBLK (NTILES * (NTILES + 1) / 2)   // 528 upper-triangular tiles
#define GRID_SIM 296        // 148 SMs x 2 CTAs, work-stealing

// Dynamic smem layout (floats)
#define AROW   260                      // 2*BM + 4 pad: 1040B row -> 16B aligned, STS.64 conflict-free
#define BROW   132                      // BN + 4 pad: 528B row -> 16B aligned
#define A_BUF  (BK * AROW)              // 4160 floats per buffer
#define B_BUF  (BK * BROW)              // 2112 floats per buffer
#define DYN_FLOATS (2 * A_BUF + 2 * B_BUF)
#define DYN_BYTES  (DYN_FLOATS * 4)     // 50176 B

// Scratch (no cudaMalloc allowed)
__device__ unsigned long long g_min[BSZ];   // packed (fkey(simval)<<32 | col)
__device__ int                g_label[BSZ];
__device__ unsigned int       g_ticket;
__device__ unsigned long long g_isum;       // fixed-point loss sum (2^20 scale)
__device__ unsigned int       g_done;

// Monotone increasing float -> uint mapping (smaller float => smaller key)
__device__ __forceinline__ unsigned int fkey(float x) {
    unsigned int u = __float_as_uint(x);
    return (u & 0x80000000u) ? ~u : (u | 0x80000000u);
}

// Packed f32x2 FMA (Blackwell FFMA2 path)
#define FMA2(d, a, b) \
    asm("fma.rn.f32x2 %0, %1, %2, %0;" : "+l"(d) : "l"(a), "l"(b))
#define UNPK2(lo, hi, d) \
    asm("mov.b64 {%0, %1}, %2;" : "=f"(lo), "=f"(hi) : "l"(d))

// ---------------------------------------------------------------------------
// Prologue: label dtype sniff (int32 vs little-endian int64), init g_min,
// reset ticket / loss-sum / done counters (graph-replay safe).
// ---------------------------------------------------------------------------
__global__ void prologue_kernel(const int* __restrict__ lab32) {
    __shared__ int is64;
    if (threadIdx.x == 0) {
        int odd_or = 0;
        #pragma unroll
        for (int i = 0; i < 32; i++) odd_or |= lab32[2 * i + 1];
        is64 = (odd_or == 0) ? 1 : 0;
        if (blockIdx.x == 0) { g_ticket = 0u; g_isum = 0ull; g_done = 0u; }
    }
    __syncthreads();
    const int i = blockIdx.x * blockDim.x + threadIdx.x;
    if (i < BSZ) {
        g_label[i] = is64 ? lab32[2 * i] : lab32[i];
        g_min[i]   = 0xFFFFFFFFFFFFFFFFull;
    }
}

// ---------------------------------------------------------------------------
// Persistent work-stealing sim tiles + bidirectional masked argmin over the
// upper triangle. 256 threads, 128x128 tile, 8x8 per thread via packed f32x2.
// A tile stored DUPLICATED in smem ([v,v] pairs) so the broadcast operand for
// FMA2 loads directly as a packed pair -> no per-k DUP movs.
// ---------------------------------------------------------------------------
__global__ __launch_bounds__(256, 2)
void sim_argmin_kernel(const float* __restrict__ ftr) {
    extern __shared__ __align__(16) float dsm[];
    float* const Asd = dsm;                 // [2][BK][AROW], values duplicated
    float* const Bsf = dsm + 2 * A_BUF;     // [2][BK][BROW]

    __shared__ unsigned long long rowMin[BM];
    __shared__ unsigned long long colMin[BN];
    __shared__ int slabR[BM];
    __shared__ int slabC[BN];
    __shared__ int s_tile;

    const int tid = threadIdx.x;
    const int tx  = tid & 15;
    const int ty  = tid >> 4;

    for (;;) {
        if (tid == 0) s_tile = (int)atomicAdd(&g_ticket, 1u);
        __syncthreads();
        const int tile = s_tile;
        if (tile >= NBLK) break;

        // triangular decode: tile -> (bi, bj), bi <= bj
        int t = tile, bi = 0;
        #pragma unroll 1
        for (;;) {
            const int len = NTILES - bi;
            if (t < len) break;
            t -= len;
            bi++;
        }
        const int bj   = bi + t;
        const int row0 = bi * BM;
        const int col0 = bj * BN;
        const bool offdiag = (bi != bj);

        if (tid < BM) {
            rowMin[tid] = 0xFFFFFFFFFFFFFFFFull;
            colMin[tid] = 0xFFFFFFFFFFFFFFFFull;
            slabR[tid]  = g_label[row0 + tid];
            slabC[tid]  = g_label[col0 + tid];
        }

        // acc as packed f32x2: 8 rows x 4 col-pairs
        unsigned long long acc2[8][4];
        #pragma unroll
        for (int i = 0; i < 8; i++)
            #pragma unroll
            for (int j = 0; j < 4; j++)
                acc2[i][j] = 0ull;

        // ---- preload k-tile 0 ----
        {
            #pragma unroll
            for (int l = 0; l < 2; l++) {
                int f = tid + l * 256;
                int r = f >> 2, kq = f & 3;
                float4 va = *(const float4*)(ftr + (size_t)(row0 + r) * DD + kq * 4);
                float4 vb = *(const float4*)(ftr + (size_t)(col0 + r) * DD + kq * 4);
                #pragma unroll
                for (int c = 0; c < 4; c++) {
                    const float v = (&va.x)[c];
                    *(float2*)&Asd[(kq * 4 + c) * AROW + 2 * r] = make_float2(v, v);
                }
                Bsf[(kq * 4 + 0) * BROW + r] = vb.x;
                Bsf[(kq * 4 + 1) * BROW + r] = vb.y;
                Bsf[(kq * 4 + 2) * BROW + r] = vb.z;
                Bsf[(kq * 4 + 3) * BROW + r] = vb.w;
            }
        }
        __syncthreads();

        // ---- main loop over k-tiles, double buffered ----
        for (int kt = 0; kt < NT; kt++) {
            const int cur = kt & 1;
            float4 va[2], vb[2];
            const bool more = (kt + 1) < NT;

            if (more) {
                const int k0 = (kt + 1) * BK;
                #pragma unroll
                for (int l = 0; l < 2; l++) {
                    int f = tid + l * 256;
                    int r = f >> 2, kq = f & 3;
                    va[l] = *(const float4*)(ftr + (size_t)(row0 + r) * DD + k0 + kq * 4);
                    vb[l] = *(const float4*)(ftr + (size_t)(col0 + r) * DD + k0 + kq * 4);
                }
            }

            const float* Ab = Asd + cur * A_BUF + 16 * ty;
            const float* Bb = Bsf + cur * B_BUF + 8 * tx;
            #pragma unroll
            for (int k = 0; k < BK; k++) {
                // packed (a_i, a_i) pairs, straight from duplicated smem
                ulonglong2 aq0 = *(const ulonglong2*)(Ab + k * AROW + 0);
                ulonglong2 aq1 = *(const ulonglong2*)(Ab + k * AROW + 4);
                ulonglong2 aq2 = *(const ulonglong2*)(Ab + k * AROW + 8);
                ulonglong2 aq3 = *(const ulonglong2*)(Ab + k * AROW + 12);
                const unsigned long long ad[8] =
                    {aq0.x, aq0.y, aq1.x, aq1.y, aq2.x, aq2.y, aq3.x, aq3.y};
                // packed B col-pairs
                ulonglong2 b01 = *(const ulonglong2*)(Bb + k * BROW + 0);
                ulonglong2 b23 = *(const ulonglong2*)(Bb + k * BROW + 4);
                const unsigned long long b2[4] = {b01.x, b01.y, b23.x, b23.y};
                #pragma unroll
                for (int i = 0; i < 8; i++) {
                    FMA2(acc2[i][0], ad[i], b2[0]);
                    FMA2(acc2[i][1], ad[i], b2[1]);
                    FMA2(acc2[i][2], ad[i], b2[2]);
                    FMA2(acc2[i][3], ad[i], b2[3]);
                }
            }

            if (more) {
                const int nb = cur ^ 1;
                #pragma unroll
                for (int l = 0; l < 2; l++) {
                    int f = tid + l * 256;
                    int r = f >> 2, kq = f & 3;
                    #pragma unroll
                    for (int c = 0; c < 4; c++) {
                        const float v = (&va[l].x)[c];
                        *(float2*)&Asd[nb * A_BUF + (kq * 4 + c) * AROW + 2 * r] =
                            make_float2(v, v);
                    }
                    Bsf[nb * B_BUF + (kq * 4 + 0) * BROW + r] = vb[l].x;
                    Bsf[nb * B_BUF + (kq * 4 + 1) * BROW + r] = vb[l].y;
                    Bsf[nb * B_BUF + (kq * 4 + 2) * BROW + r] = vb[l].z;
                    Bsf[nb * B_BUF + (kq * 4 + 3) * BROW + r] = vb[l].w;
                }
            }
            __syncthreads();
        }

        // unpack accumulators
        float acc[8][8];
        #pragma unroll
        for (int i = 0; i < 8; i++)
            #pragma unroll
            for (int j = 0; j < 4; j++)
                UNPK2(acc[i][2 * j], acc[i][2 * j + 1], acc2[i][j]);

        // ---- epilogue: row-direction masked argmin ----
        #pragma unroll
        for (int i = 0; i < 8; i++) {
            const int gi  = ty * 8 + i;
            const int lab = slabR[gi];
            unsigned long long best = 0xFFFFFFFFFFFFFFFFull;
            #pragma unroll
            for (int j = 0; j < 8; j++) {
                const int gj = col0 + tx * 8 + j;
                if (gj != lab) {
                    unsigned long long p =
                        ((unsigned long long)fkey(acc[i][j]) << 32) | (unsigned int)gj;
                    best = (p < best) ? p : best;
                }
            }
            atomicMin(&rowMin[gi], best);
        }

        // ---- epilogue: col-direction (transposed) masked argmin ----
        if (offdiag) {
            #pragma unroll
            for (int j = 0; j < 8; j++) {
                const int gj  = tx * 8 + j;
                const int lab = slabC[gj];
                unsigned long long best = 0xFFFFFFFFFFFFFFFFull;
                #pragma unroll
                for (int i = 0; i < 8; i++) {
                    const int gi = row0 + ty * 8 + i;
                    if (gi != lab) {
                        unsigned long long p =
                            ((unsigned long long)fkey(acc[i][j]) << 32) | (unsigned int)gi;
                        best = (p < best) ? p : best;
                    }
                }
                atomicMin(&colMin[gj], best);
            }
        }
        __syncthreads();

        if (tid < BM) {
            atomicMin(&g_min[row0 + tid], rowMin[tid]);
            if (offdiag) atomicMin(&g_min[col0 + tid], colMin[tid]);
        }
        __syncthreads();
    }
}

// ---------------------------------------------------------------------------
// Fused loss + mean: one warp per row; deterministic fixed-point global sum
// (integer atomics are exact & commutative -> bit-stable across replays);
// last block finalizes the mean.
// ---------------------------------------------------------------------------
__global__ __launch_bounds__(256)
void loss_reduce_kernel(const float* __restrict__ ftr,
                        const float* __restrict__ prototypes,
                        float* __restrict__ out) {
    const int warp = (blockIdx.x * blockDim.x + threadIdx.x) >> 5;
    const int lane = threadIdx.x & 31;
    const int r    = warp;
    const int lab  = g_label[r];
    const int ni   = (int)(g_min[r] & 0xFFFFFFFFull);

    const float* xp = ftr + (size_t)r * DD;
    const float* yp = prototypes + (size_t)lab * DD;
    const float* np = ftr + (size_t)ni * DD;

    float pd = 0.0f, nd = 0.0f;
    #pragma unroll
    for (int t = 0; t < DD / 32; t++) {
        const int c = lane + t * 32;
        const float xv = xp[c];
        const float dy = xv - yp[c];
        const float dn = xv - np[c];
        pd = fmaf(dy, dy, pd);
        nd = fmaf(dn, dn, nd);
    }
    #pragma unroll
    for (int o = 16; o > 0; o >>= 1) {
        pd += __shfl_down_sync(0xFFFFFFFFu, pd, o);
        nd += __shfl_down_sync(0xFFFFFFFFu, nd, o);
    }
    if (lane == 0) {
        const float loss = fmaxf(pd - nd + MARGIN, 0.0f);
        atomicAdd(&g_isum, (unsigned long long)(long long)llrintf(loss * 1048576.0f));
    }
    __syncthreads();
    if (threadIdx.x == 0) {
        __threadfence();
        const unsigned int old = atomicAdd(&g_done, 1u);
        if (old == gridDim.x - 1) {
            __threadfence();
            const long long s = (long long)*(volatile unsigned long long*)&g_isum;
            out[0] = (float)((double)s / ((double)BSZ * 1048576.0));
        }
    }
}

extern "C" void kernel_launch(void* const* d_in, const int* in_sizes, int n_in,
                              void* d_out, int out_size) {
    const float* ftr        = (const float*)d_in[0];
    // d_in[1] = teachor_ftr : unused by the reference computation
    const float* prototypes = (const float*)d_in[2];
    const int*   label_raw  = (const int*)d_in[3];   // int32 or int64 — sniffed on device
    float*       out        = (float*)d_out;

    cudaFuncSetAttribute(sim_argmin_kernel,
                         cudaFuncAttributeMaxDynamicSharedMemorySize, DYN_BYTES);

    prologue_kernel<<<BSZ / 256, 256>>>(label_raw);

    sim_argmin_kernel<<<GRID_SIM, 256, DYN_BYTES>>>(ftr);  // stealing over 528 tiles

    loss_reduce_kernel<<<(BSZ * 32) / 256, 256>>>(ftr, prototypes, out);
}